// round 13
// baseline (speedup 1.0000x reference)
#include <cuda_runtime.h>
#include <cuda_fp16.h>
#include <cstdint>

#define HIDDEN    2048
#define INTER     5504
#define INTER_PAD 5632            /* 22 * 256 */
#define NFUSED    (2 * INTER_PAD) /* interleaved gate/up rows: 11264 = 44*256 */
#define TSTEPS    4
#define MROWS     4096            /* T*BSZ*SEQ */
#define BSROWS    1024            /* BSZ*SEQ */

#define KTILE     64              /* fp16 K-elements per tile: 128B rows */
#define STAGES    3
#define BUF_BYTES 49152           /* A 16KB + B 32KB */
#define DYN_SMEM  (STAGES * BUF_BYTES)   /* 144 KB */

// ---------------- scratch (device globals; no allocation allowed) ----------
// Row order of g_X / g_C: reordered M, row = bs*4 + t  (t minor).
__device__ __half g_X  [(size_t)MROWS * HIDDEN];
__device__ __half g_WGU[(size_t)NFUSED * HIDDEN];   /* row 2i = gate_i, 2i+1 = up_i */
__device__ __half g_WD [(size_t)HIDDEN * INTER_PAD];
__device__ __half g_C  [(size_t)MROWS * INTER_PAD]; /* combine output, reordered rows */

// ---------------- helpers ----------------------------------------------------
__device__ __forceinline__ uint32_t smem_u32(const void* p) {
    uint32_t a;
    asm("{ .reg .u64 t; cvta.to.shared.u64 t, %1; cvt.u32.u64 %0, t; }" : "=r"(a) : "l"(p));
    return a;
}

#define CP_ASYNC16(dst, src) \
    asm volatile("cp.async.cg.shared.global [%0], [%1], 16;" :: "r"(dst), "l"(src))
#define CP_COMMIT() asm volatile("cp.async.commit_group;" ::: "memory")
#define CP_WAIT1()  asm volatile("cp.async.wait_group 1;"  ::: "memory")

#define LDSM_X4(r0, r1, r2, r3, addr) \
    asm volatile("ldmatrix.sync.aligned.m8n8.x4.shared.b16 {%0,%1,%2,%3}, [%4];" \
                 : "=r"(r0), "=r"(r1), "=r"(r2), "=r"(r3) : "r"(addr))

__device__ __forceinline__ void mma_f16(float* d, const uint32_t* a, const uint32_t* b) {
    asm volatile(
        "mma.sync.aligned.m16n8k16.row.col.f32.f16.f16.f32 "
        "{%0,%1,%2,%3}, {%4,%5,%6,%7}, {%8,%9}, {%0,%1,%2,%3};\n"
        : "+f"(d[0]), "+f"(d[1]), "+f"(d[2]), "+f"(d[3])
        : "r"(a[0]), "r"(a[1]), "r"(a[2]), "r"(a[3]), "r"(b[0]), "r"(b[1]));
}

// Per-element SNN combine across the 4-lane t-group (stride 4 within 16 lanes).
__device__ __forceinline__ float snn_combine(float gate, float up, int t) {
    const unsigned FULL = 0xffffffffu;
    float X = gate, tmp;
    tmp = __shfl_up_sync(FULL, X, 4);  if (t >= 1) X += tmp;
    tmp = __shfl_up_sync(FULL, X, 8);  if (t >= 2) X += tmp;
    const float Y = X / (1.f + expf(-X));            // silu of cumsum
    tmp = __shfl_up_sync(FULL, Y, 4);
    const float Av = (t >= 1) ? (Y - tmp) : Y;       // delta
    const int lane = (int)(threadIdx.x & 31);
    const float SA = __shfl_sync(FULL, Y, lane | 12);  // Y at t=3 (= sum_t A)
    float SB = up;
    SB += __shfl_xor_sync(FULL, SB, 4);
    SB += __shfl_xor_sync(FULL, SB, 8);
    return 0.5f * (Av * SB + up * SA);
}

// ---------------- GEMM: acc[m,n] = sum_k A[m,k]*B[n,k] ----------------------
// Block tile 128x256, 256 threads, 8 warps (2x4), warp tile 64x64.
// cp.async 3-stage ring, one barrier per K-tile, LDSM fragment loads,
// m16n8k16 fp16 MMA, fp32 accumulation.
// MODE 0: fused gate/up GEMM + in-epilogue SNN combine -> fp16 C.
// MODE 1: down GEMM, row un-permute (bs*4+t -> t*1024+bs) -> fp32.
// Requires M%128==0, N%256==0, K%64==0, NK>=2.
template <int MODE>
__global__ void __launch_bounds__(256, 1)
gemm_tn(const __half* __restrict__ A, const __half* __restrict__ B,
        void* __restrict__ Cout, int K, int N)
{
    extern __shared__ __align__(16) uint8_t smraw[];
    const uint32_t sb = smem_u32(smraw);

    const int tid  = threadIdx.x;
    const int lane = tid & 31;
    const int warp = tid >> 5;
    const int wm   = warp & 1;   // 2 warp rows of 64
    const int wn   = warp >> 1;  // 4 warp cols of 64

    const int r = tid >> 3;      // 0..31 : row within group of 32 (fill map)
    const int c = tid & 7;       // 0..7  : 16B (k8) atom within 128B row

    // LDSM per-lane selectors (verified bit-exact since R4):
    const int rsel   = lane & 7;
    const int a_k8hi = lane >> 4;
    const int a_moff = ((lane >> 3) & 1) << 3;
    const int b_k8lo = (lane >> 3) & 1;
    const int b_noff = (lane >> 4) << 3;
    const int mrowA  = wm * 64 + a_moff + rsel;
    const int nrowB  = wn * 64 + b_noff + rsel;

    const size_t mBase = (size_t)blockIdx.y * 128;
    const size_t nBase = (size_t)blockIdx.x * 256;
    const int NK = K / KTILE;

    const __half* Ag = A + (mBase + (size_t)r) * (size_t)K + (size_t)c * 8;
    const __half* Bg = B + (nBase + (size_t)r) * (size_t)K + (size_t)c * 8;

    // Stage layout: A atoms [k8(0..7)][m(0..127)] 16B at slot m^k8;
    //               B atoms [k8(0..7)][n(0..255)] 16B at slot n^k8 (at +16KB).
    auto fill = [&](int s, int kt) {
        const uint32_t abase = sb + (uint32_t)s * BUF_BYTES;
        const uint32_t bbase = abase + 16384;
        const __half* Ak = Ag + (size_t)kt * KTILE;
        const __half* Bk = Bg + (size_t)kt * KTILE;
        #pragma unroll
        for (int j = 0; j < 4; ++j) {
            const int m = j * 32 + r;
            CP_ASYNC16(abase + ((uint32_t)(c * 128 + (m ^ c)) << 4),
                       Ak + (size_t)(j * 32) * K);
        }
        #pragma unroll
        for (int j = 0; j < 8; ++j) {
            const int n = j * 32 + r;
            CP_ASYNC16(bbase + ((uint32_t)(c * 256 + (n ^ c)) << 4),
                       Bk + (size_t)(j * 32) * K);
        }
    };

    float acc[4][8][4];
    #pragma unroll
    for (int i = 0; i < 4; ++i)
        #pragma unroll
        for (int j = 0; j < 8; ++j)
            #pragma unroll
            for (int q = 0; q < 4; ++q) acc[i][j][q] = 0.f;

    // prologue: two tiles in flight
    fill(0, 0); CP_COMMIT();
    fill(1, 1); CP_COMMIT();

    int stage = 0;
    for (int kt = 0; kt < NK; ++kt) {
        CP_WAIT1();          // group for tile kt complete (kt+1 may fly)
        __syncthreads();     // writes visible to all; stage (kt+2)%3 free

        if (kt + 2 < NK) {
            int fs = stage + 2;
            if (fs >= STAGES) fs -= STAGES;   // correct ring index in {0,1,2}
            fill(fs, kt + 2);
        }
        CP_COMMIT();         // one group per iteration (empty at tail)

        const uint32_t abase = sb + (uint32_t)stage * BUF_BYTES;
        const uint32_t bbase = abase + 16384;

        #pragma unroll
        for (int ks = 0; ks < 4; ++ks) {        // 4 k16-steps over 64-K tile
            const uint32_t ak8 = (uint32_t)(ks * 2 + a_k8hi);
            const uint32_t bk8 = (uint32_t)(ks * 2 + b_k8lo);

            uint32_t af[4][4];
            #pragma unroll
            for (int im = 0; im < 4; ++im) {
                const uint32_t m = (uint32_t)(mrowA + im * 16);
                const uint32_t addr = abase + (ak8 << 11) + (((m ^ ak8) & 127u) << 4);
                LDSM_X4(af[im][0], af[im][1], af[im][2], af[im][3], addr);
            }
            uint32_t bf[8][2];
            #pragma unroll
            for (int p = 0; p < 4; ++p) {
                const uint32_t n = (uint32_t)(nrowB + p * 16);
                const uint32_t addr = bbase + (bk8 << 12) + (((n ^ bk8) & 255u) << 4);
                LDSM_X4(bf[2 * p][0], bf[2 * p][1], bf[2 * p + 1][0], bf[2 * p + 1][1], addr);
            }
            #pragma unroll
            for (int im = 0; im < 4; ++im)
                #pragma unroll
                for (int jn = 0; jn < 8; ++jn)
                    mma_f16(acc[im][jn], af[im], bf[jn]);
        }

        stage = (stage + 1 == STAGES) ? 0 : stage + 1;
    }

    // -------- epilogue --------
    const int g  = lane >> 2;          // row-in-8 selector
    const int l3 = lane & 3;
    const int t  = g & 3;              // rows g and g+8 share t = g&3

    if constexpr (MODE == 0) {
        __half* C = (__half*)Cout;
        const size_t ccBase = (nBase >> 1) + (size_t)wn * 32;
        #pragma unroll
        for (int im = 0; im < 4; ++im) {
            const size_t row0 = mBase + wm * 64 + im * 16 + g;
            #pragma unroll
            for (int jn = 0; jn < 8; ++jn) {
                const size_t cc = ccBase + jn * 4 + l3;   // C col = gate col / 2
                const float c0 = snn_combine(acc[im][jn][0], acc[im][jn][1], t);
                const float c1 = snn_combine(acc[im][jn][2], acc[im][jn][3], t);
                C[row0 * INTER_PAD + cc]       = __float2half_rn(c0);
                C[(row0 + 8) * INTER_PAD + cc] = __float2half_rn(c1);
            }
        }
    } else {
        float* C = (float*)Cout;
        const int q2 = l3 * 2;
        #pragma unroll
        for (int im = 0; im < 4; ++im) {
            const size_t row0 = mBase + wm * 64 + im * 16 + g;
            const size_t row1 = row0 + 8;
            const size_t o0 = (row0 & 3) * BSROWS + (row0 >> 2);
            const size_t o1 = (row1 & 3) * BSROWS + (row1 >> 2);
            #pragma unroll
            for (int jn = 0; jn < 8; ++jn) {
                const size_t col0 = nBase + wn * 64 + jn * 8 + q2;
                *(float2*)&C[o0 * (size_t)N + col0] =
                    make_float2(acc[im][jn][0], acc[im][jn][1]);
                *(float2*)&C[o1 * (size_t)N + col0] =
                    make_float2(acc[im][jn][2], acc[im][jn][3]);
            }
        }
    }
}

// ---------------- prepass kernels -------------------------------------------
__device__ __forceinline__ void store_h4(__half* dst, float4 v) {
    __half2* d2 = reinterpret_cast<__half2*>(dst);
    d2[0] = __floats2half2_rn(v.x, v.y);
    d2[1] = __floats2half2_rn(v.z, v.w);
}

// x: src row = t*BSROWS + bs  ->  dst row = bs*4 + t  (t minor), fp16.
__global__ void x_perm_k(const float* __restrict__ src, __half* __restrict__ dst, long n4)
{
    long i = (long)blockIdx.x * blockDim.x + threadIdx.x;
    if (i >= n4) return;
    long e = i * 4;
    int drow = (int)(e / HIDDEN);
    int col  = (int)(e % HIDDEN);
    int bs = drow >> 2, tt = drow & 3;
    const size_t srow = (size_t)tt * BSROWS + bs;
    store_h4(dst + e, *(const float4*)(src + srow * HIDDEN + col));
}

// fused weight: dst row 2i = gate_i, 2i+1 = up_i; rows i>=INTER zero-filled.
__global__ void w_interleave_k(const float* __restrict__ wg, const float* __restrict__ wu,
                               __half* __restrict__ dst, long n4)
{
    long i = (long)blockIdx.x * blockDim.x + threadIdx.x;
    if (i >= n4) return;
    long e = i * 4;
    int drow = (int)(e / HIDDEN);
    int col  = (int)(e % HIDDEN);
    int srow = drow >> 1;
    float4 v = make_float4(0.f, 0.f, 0.f, 0.f);
    if (srow < INTER) {
        const float* src = (drow & 1) ? wu : wg;
        v = *(const float4*)(src + (size_t)srow * HIDDEN + col);
    }
    store_h4(dst + e, v);
}

// w_down: dst [rows x cols_pad]; pad cols zero-filled.
__global__ void h_pad_cols_k(const float* __restrict__ src, __half* __restrict__ dst,
                             int cols_src, int cols_pad, long n4)
{
    long i = (long)blockIdx.x * blockDim.x + threadIdx.x;
    if (i >= n4) return;
    long e = i * 4;
    int row = (int)(e / cols_pad);
    int col = (int)(e % cols_pad);
    float4 v = make_float4(0.f, 0.f, 0.f, 0.f);
    if (col < cols_src)
        v = *(const float4*)(src + (size_t)row * cols_src + col);
    store_h4(dst + e, v);
}

// ---------------- launch -----------------------------------------------------
extern "C" void kernel_launch(void* const* d_in, const int* in_sizes, int n_in,
                              void* d_out, int out_size)
{
    const float* x      = (const float*)d_in[0];
    const float* w_gate = (const float*)d_in[1];
    const float* w_up   = (const float*)d_in[2];
    const float* w_down = (const float*)d_in[3];
    float* out = (float*)d_out;
    (void)in_sizes; (void)n_in; (void)out_size;

    __half *dX, *dWGU, *dWD, *dC;
    cudaGetSymbolAddress((void**)&dX,   g_X);
    cudaGetSymbolAddress((void**)&dWGU, g_WGU);
    cudaGetSymbolAddress((void**)&dWD,  g_WD);
    cudaGetSymbolAddress((void**)&dC,   g_C);

    cudaFuncSetAttribute(gemm_tn<0>, cudaFuncAttributeMaxDynamicSharedMemorySize, DYN_SMEM);
    cudaFuncSetAttribute(gemm_tn<1>, cudaFuncAttributeMaxDynamicSharedMemorySize, DYN_SMEM);

    // Prepass: fp32 -> fp16; x rows t-minor; gate/up interleaved; w_down padded.
    {
        long n4 = (long)MROWS * HIDDEN / 4;
        x_perm_k<<<(unsigned)((n4 + 255) / 256), 256>>>(x, dX, n4);
        long w4 = (long)NFUSED * HIDDEN / 4;
        w_interleave_k<<<(unsigned)((w4 + 255) / 256), 256>>>(w_gate, w_up, dWGU, w4);
        long d4 = (long)HIDDEN * INTER_PAD / 4;
        h_pad_cols_k<<<(unsigned)((d4 + 255) / 256), 256>>>(w_down, dWD, INTER, INTER_PAD, d4);
    }

    // Fused gate+up GEMM with in-epilogue SNN combine -> fp16 C (reordered rows).
    {
        dim3 grid(NFUSED / 256, MROWS / 128);      // 44 x 32
        gemm_tn<0><<<grid, 256, DYN_SMEM>>>(dX, dWGU, dC, HIDDEN, NFUSED);
    }

    // Down projection with row un-permute -> fp32 out.
    {
        dim3 grid(HIDDEN / 256, MROWS / 128);      // 8 x 32
        gemm_tn<1><<<grid, 256, DYN_SMEM>>>(dC, dWD, out, INTER_PAD, HIDDEN);
    }
}

// round 14
// speedup vs baseline: 1.7493x; 1.7493x over previous
#include <cuda_runtime.h>
#include <cuda_fp16.h>
#include <cstdint>

#define HIDDEN    2048
#define INTER     5504
#define INTER_PAD 5632            /* 22 * 256 */
#define NFUSED    (2 * INTER_PAD) /* interleaved gate/up rows: 11264 = 44*256 */
#define TSTEPS    4
#define MROWS     4096            /* T*BSZ*SEQ */
#define BSROWS    1024            /* BSZ*SEQ */

#define KTILE     64              /* fp16 K-elements per tile: 128B rows */
#define BUF_BYTES 49152           /* A 16KB + B 32KB */
#define DYN_SMEM  (2 * BUF_BYTES) /* 96 KB; also holds the 34.8KB epilogue stage */

// ---------------- scratch (device globals; no allocation allowed) ----------
// Row order of g_X / g_C: reordered M, row = bs*4 + t  (t minor).
__device__ __half g_X  [(size_t)MROWS * HIDDEN];
__device__ __half g_WGU[(size_t)NFUSED * HIDDEN];   /* row 2i = gate_i, 2i+1 = up_i */
__device__ __half g_WD [(size_t)HIDDEN * INTER_PAD];
__device__ __half g_C  [(size_t)MROWS * INTER_PAD]; /* combine output, reordered rows */

// ---------------- helpers ----------------------------------------------------
__device__ __forceinline__ uint32_t smem_u32(const void* p) {
    uint32_t a;
    asm("{ .reg .u64 t; cvta.to.shared.u64 t, %1; cvt.u32.u64 %0, t; }" : "=r"(a) : "l"(p));
    return a;
}

#define LDSM_X4(r0, r1, r2, r3, addr) \
    asm volatile("ldmatrix.sync.aligned.m8n8.x4.shared.b16 {%0,%1,%2,%3}, [%4];" \
                 : "=r"(r0), "=r"(r1), "=r"(r2), "=r"(r3) : "r"(addr))

__device__ __forceinline__ void mma_f16(float* d, const uint32_t* a, const uint32_t* b) {
    asm volatile(
        "mma.sync.aligned.m16n8k16.row.col.f32.f16.f16.f32 "
        "{%0,%1,%2,%3}, {%4,%5,%6,%7}, {%8,%9}, {%0,%1,%2,%3};\n"
        : "+f"(d[0]), "+f"(d[1]), "+f"(d[2]), "+f"(d[3])
        : "r"(a[0]), "r"(a[1]), "r"(a[2]), "r"(a[3]), "r"(b[0]), "r"(b[1]));
}

// Per-element SNN combine across the 4-lane t-group (stride 4 within 16 lanes).
// Verified bit-exact in R10 (rel_err 5.2222e-4).
__device__ __forceinline__ float snn_combine(float gate, float up, int t) {
    const unsigned FULL = 0xffffffffu;
    float X = gate, tmp;
    tmp = __shfl_up_sync(FULL, X, 4);  if (t >= 1) X += tmp;
    tmp = __shfl_up_sync(FULL, X, 8);  if (t >= 2) X += tmp;
    const float Y = X / (1.f + expf(-X));            // silu of cumsum
    tmp = __shfl_up_sync(FULL, Y, 4);
    const float Av = (t >= 1) ? (Y - tmp) : Y;       // delta
    const int lane = (int)(threadIdx.x & 31);
    const float SA = __shfl_sync(FULL, Y, lane | 12);  // Y at t=3 (= sum_t A)
    float SB = up;
    SB += __shfl_xor_sync(FULL, SB, 4);
    SB += __shfl_xor_sync(FULL, SB, 8);
    return 0.5f * (Av * SB + up * SA);
}

// ---------------- GEMM: acc[m,n] = sum_k A[m,k]*B[n,k] ----------------------
// Block tile 128x256, 256 threads, 8 warps (2x4), warp tile 64x64.
// Register-prefetched globals, double-buffered smem, one barrier per K-tile,
// LDSM fragment loads, m16n8k16 fp16 MMA, fp32 accumulation. (R10 mainloop.)
// MODE 0: fused gate/up GEMM + in-epilogue SNN combine, smem-staged coalesced
//         fp16 stores to C (128 C-cols per block).
// MODE 1: down GEMM, row un-permute (bs*4+t -> t*1024+bs) -> fp32.
// Requires M%128==0, N%256==0, K%64==0.
template <int MODE>
__global__ void __launch_bounds__(256, 1)
gemm_tn(const __half* __restrict__ A, const __half* __restrict__ B,
        void* __restrict__ Cout, int K, int N)
{
    extern __shared__ __align__(16) uint8_t smraw[];
    uint4* sm = reinterpret_cast<uint4*>(smraw);
    const uint32_t sb = smem_u32(smraw);

    const int tid  = threadIdx.x;
    const int lane = tid & 31;
    const int warp = tid >> 5;
    const int wm   = warp & 1;   // 2 warp rows of 64
    const int wn   = warp >> 1;  // 4 warp cols of 64

    const int r = tid >> 3;      // 0..31 : row within group of 32 (ldg/sts map)
    const int c = tid & 7;       // 0..7  : 16B (k8) atom within 128B row

    // LDSM per-lane selectors (verified bit-exact since R4):
    const int rsel   = lane & 7;
    const int a_k8hi = lane >> 4;
    const int a_moff = ((lane >> 3) & 1) << 3;
    const int b_k8lo = (lane >> 3) & 1;
    const int b_noff = (lane >> 4) << 3;
    const int mrowA  = wm * 64 + a_moff + rsel;
    const int nrowB  = wn * 64 + b_noff + rsel;

    const size_t mBase = (size_t)blockIdx.y * 128;
    const size_t nBase = (size_t)blockIdx.x * 256;
    const int NK = K / KTILE;

    const __half* Ag = A + (mBase + (size_t)r) * (size_t)K + (size_t)c * 8;
    const __half* Bg = B + (nBase + (size_t)r) * (size_t)K + (size_t)c * 8;

    uint4 pa[4], pb[8];

    auto ldg_tile = [&](int kt) {
        const __half* Ak = Ag + (size_t)kt * KTILE;
        const __half* Bk = Bg + (size_t)kt * KTILE;
        #pragma unroll
        for (int j = 0; j < 4; ++j)
            pa[j] = *(const uint4*)(Ak + (size_t)(j * 32) * K);
        #pragma unroll
        for (int j = 0; j < 8; ++j)
            pb[j] = *(const uint4*)(Bk + (size_t)(j * 32) * K);
    };
    auto sts_tile = [&](int buf) {
        uint4* As = sm + buf * (BUF_BYTES / 16);
        uint4* Bs = As + 1024;
        #pragma unroll
        for (int j = 0; j < 4; ++j) {
            const int m = j * 32 + r;
            As[c * 128 + (m ^ c)] = pa[j];
        }
        #pragma unroll
        for (int j = 0; j < 8; ++j) {
            const int n = j * 32 + r;
            Bs[c * 256 + (n ^ c)] = pb[j];
        }
    };

    float acc[4][8][4];
    #pragma unroll
    for (int i = 0; i < 4; ++i)
        #pragma unroll
        for (int j = 0; j < 8; ++j)
            #pragma unroll
            for (int q = 0; q < 4; ++q) acc[i][j][q] = 0.f;

    // prologue
    ldg_tile(0);
    sts_tile(0);
    if (NK > 1) ldg_tile(1);
    __syncthreads();

    for (int kt = 0; kt < NK; ++kt) {
        if (kt + 1 < NK) {
            sts_tile((kt + 1) & 1);
            if (kt + 2 < NK) ldg_tile(kt + 2);
        }

        const uint32_t abase = sb + (uint32_t)((kt & 1) * BUF_BYTES);
        const uint32_t bbase = abase + 16384;

        #pragma unroll
        for (int ks = 0; ks < 4; ++ks) {        // 4 k16-steps over 64-K tile
            const uint32_t ak8 = (uint32_t)(ks * 2 + a_k8hi);
            const uint32_t bk8 = (uint32_t)(ks * 2 + b_k8lo);

            uint32_t af[4][4];
            #pragma unroll
            for (int im = 0; im < 4; ++im) {
                const uint32_t m = (uint32_t)(mrowA + im * 16);
                const uint32_t addr = abase + (ak8 << 11) + (((m ^ ak8) & 127u) << 4);
                LDSM_X4(af[im][0], af[im][1], af[im][2], af[im][3], addr);
            }
            uint32_t bf[8][2];
            #pragma unroll
            for (int p = 0; p < 4; ++p) {
                const uint32_t n = (uint32_t)(nrowB + p * 16);
                const uint32_t addr = bbase + (bk8 << 12) + (((n ^ bk8) & 255u) << 4);
                LDSM_X4(bf[2 * p][0], bf[2 * p][1], bf[2 * p + 1][0], bf[2 * p + 1][1], addr);
            }
            #pragma unroll
            for (int im = 0; im < 4; ++im)
                #pragma unroll
                for (int jn = 0; jn < 8; ++jn)
                    mma_f16(acc[im][jn], af[im], bf[jn]);
        }
        __syncthreads();
    }

    // -------- epilogue --------
    const int g  = lane >> 2;          // row-in-8 selector
    const int l3 = lane & 3;
    const int t  = g & 3;              // rows g and g+8 share t = g&3

    if constexpr (MODE == 0) {
        // Combine across t, stage fp16 results in smem (row stride 136 halves =
        // 272B, conflict-managed), then fully coalesced STG.128 to C.
        // (Mainloop ended with __syncthreads(): smem is free to reuse.)
        __half* S = reinterpret_cast<__half*>(smraw);
        #pragma unroll
        for (int im = 0; im < 4; ++im) {
            const int srow0 = wm * 64 + im * 16 + g;
            #pragma unroll
            for (int jn = 0; jn < 8; ++jn) {
                const int scol = wn * 32 + jn * 4 + l3;   // block-local C col 0..127
                const float c0 = snn_combine(acc[im][jn][0], acc[im][jn][1], t);
                const float c1 = snn_combine(acc[im][jn][2], acc[im][jn][3], t);
                S[srow0 * 136 + scol]       = __float2half_rn(c0);
                S[(srow0 + 8) * 136 + scol] = __float2half_rn(c1);
            }
        }
        __syncthreads();

        __half* C = (__half*)Cout;
        const size_t cColBase = (nBase >> 1);   // 128 C cols per block
        #pragma unroll
        for (int it = 0; it < 8; ++it) {
            const int chunk = it * 256 + tid;   // 2048 chunks of 8 halves
            const int br = chunk >> 4;          // block row 0..127
            const int c8 = (chunk & 15) << 3;   // col 0,8,...,120
            const uint4 v = *(const uint4*)(smraw + br * 272 + c8 * 2);
            *(uint4*)&C[(mBase + br) * INTER_PAD + cColBase + c8] = v;
        }
    } else {
        // Down projection: un-permute rows (bs*4+t -> t*1024+bs), store fp32.
        float* C = (float*)Cout;
        const int q2 = l3 * 2;
        #pragma unroll
        for (int im = 0; im < 4; ++im) {
            const size_t row0 = mBase + wm * 64 + im * 16 + g;
            const size_t row1 = row0 + 8;
            const size_t o0 = (row0 & 3) * BSROWS + (row0 >> 2);
            const size_t o1 = (row1 & 3) * BSROWS + (row1 >> 2);
            #pragma unroll
            for (int jn = 0; jn < 8; ++jn) {
                const size_t col0 = nBase + wn * 64 + jn * 8 + q2;
                *(float2*)&C[o0 * (size_t)N + col0] =
                    make_float2(acc[im][jn][0], acc[im][jn][1]);
                *(float2*)&C[o1 * (size_t)N + col0] =
                    make_float2(acc[im][jn][2], acc[im][jn][3]);
            }
        }
    }
}

// ---------------- fused prepass ----------------------------------------------
__device__ __forceinline__ void store_h4(__half* dst, float4 v) {
    __half2* d2 = reinterpret_cast<__half2*>(dst);
    d2[0] = __floats2half2_rn(v.x, v.y);
    d2[1] = __floats2half2_rn(v.z, v.w);
}

#define PREP_T1 ((long)MROWS * HIDDEN / 4)
#define PREP_T2 (PREP_T1 + (long)NFUSED * HIDDEN / 4)
#define PREP_T3 (PREP_T2 + (long)HIDDEN * INTER_PAD / 4)

// One launch does all three conversions:
//  [0,T1):  x  row t*BSROWS+bs -> row bs*4+t (t minor), fp16
//  [T1,T2): fused weight row 2i = gate_i, 2i+1 = up_i; rows i>=INTER zeroed
//  [T2,T3): w_down padded cols INTER -> INTER_PAD (zero fill)
__global__ void prep_k(const float* __restrict__ x,
                       const float* __restrict__ wg, const float* __restrict__ wu,
                       const float* __restrict__ wd,
                       __half* __restrict__ dX, __half* __restrict__ dWGU,
                       __half* __restrict__ dWD)
{
    long i = (long)blockIdx.x * blockDim.x + threadIdx.x;
    if (i < PREP_T1) {
        long e = i * 4;
        int drow = (int)(e / HIDDEN);
        int col  = (int)(e % HIDDEN);
        int bs = drow >> 2, tt = drow & 3;
        const size_t srow = (size_t)tt * BSROWS + bs;
        store_h4(dX + e, *(const float4*)(x + srow * HIDDEN + col));
    } else if (i < PREP_T2) {
        long e = (i - PREP_T1) * 4;
        int drow = (int)(e / HIDDEN);
        int col  = (int)(e % HIDDEN);
        int srow = drow >> 1;
        float4 v = make_float4(0.f, 0.f, 0.f, 0.f);
        if (srow < INTER) {
            const float* src = (drow & 1) ? wu : wg;
            v = *(const float4*)(src + (size_t)srow * HIDDEN + col);
        }
        store_h4(dWGU + e, v);
    } else if (i < PREP_T3) {
        long e = (i - PREP_T2) * 4;
        int row = (int)(e / INTER_PAD);
        int col = (int)(e % INTER_PAD);
        float4 v = make_float4(0.f, 0.f, 0.f, 0.f);
        if (col < INTER)
            v = *(const float4*)(wd + (size_t)row * INTER + col);
        store_h4(dWD + e, v);
    }
}

// ---------------- launch -----------------------------------------------------
extern "C" void kernel_launch(void* const* d_in, const int* in_sizes, int n_in,
                              void* d_out, int out_size)
{
    const float* x      = (const float*)d_in[0];
    const float* w_gate = (const float*)d_in[1];
    const float* w_up   = (const float*)d_in[2];
    const float* w_down = (const float*)d_in[3];
    float* out = (float*)d_out;
    (void)in_sizes; (void)n_in; (void)out_size;

    __half *dX, *dWGU, *dWD, *dC;
    cudaGetSymbolAddress((void**)&dX,   g_X);
    cudaGetSymbolAddress((void**)&dWGU, g_WGU);
    cudaGetSymbolAddress((void**)&dWD,  g_WD);
    cudaGetSymbolAddress((void**)&dC,   g_C);

    cudaFuncSetAttribute(gemm_tn<0>, cudaFuncAttributeMaxDynamicSharedMemorySize, DYN_SMEM);
    cudaFuncSetAttribute(gemm_tn<1>, cudaFuncAttributeMaxDynamicSharedMemorySize, DYN_SMEM);

    // Fused prepass (one launch).
    prep_k<<<(unsigned)((PREP_T3 + 255) / 256), 256>>>(x, w_gate, w_up, w_down,
                                                       dX, dWGU, dWD);

    // Fused gate+up GEMM with in-epilogue SNN combine -> fp16 C (reordered rows).
    {
        dim3 grid(NFUSED / 256, MROWS / 128);      // 44 x 32
        gemm_tn<0><<<grid, 256, DYN_SMEM>>>(dX, dWGU, dC, HIDDEN, NFUSED);
    }

    // Down projection with row un-permute -> fp32 out.
    {
        dim3 grid(HIDDEN / 256, MROWS / 128);      // 8 x 32
        gemm_tn<1><<<grid, 256, DYN_SMEM>>>(dC, dWD, out, INTER_PAD, HIDDEN);
    }
}

// round 15
// speedup vs baseline: 1.7798x; 1.0174x over previous
#include <cuda_runtime.h>
#include <cuda_fp16.h>
#include <cstdint>

#define HIDDEN    2048
#define INTER     5504
#define INTER_PAD 5632            /* 22 * 256 */
#define NFUSED    (2 * INTER_PAD) /* gate cols 0..5631, up cols 5632..11263 */
#define TSTEPS    4
#define MROWS     4096            /* T*BSZ*SEQ */
#define BSROWS    1024            /* BSZ*SEQ */

#define KTILE     64              /* fp16 K-elements per tile: 128B rows */
#define BUF_BYTES 49152           /* A 16KB + B 32KB */
#define DYN_SMEM  (2 * BUF_BYTES)

// ---------------- scratch (device globals; no allocation allowed) ----------
__device__ __half g_X  [(size_t)MROWS * HIDDEN];
__device__ __half g_WGU[(size_t)NFUSED * HIDDEN];   /* rows 0..5631 gate, 5632.. up */
__device__ __half g_WD [(size_t)HIDDEN * INTER_PAD];
__device__ __half g_GU [(size_t)MROWS * NFUSED];    /* fused gate/up outputs, fp16 */
__device__ __half g_C  [(size_t)MROWS * INTER_PAD]; /* combine output, fp16 */

// ---------------- helpers ----------------------------------------------------
__device__ __forceinline__ uint32_t smem_u32(const void* p) {
    uint32_t a;
    asm("{ .reg .u64 t; cvta.to.shared.u64 t, %1; cvt.u32.u64 %0, t; }" : "=r"(a) : "l"(p));
    return a;
}

#define LDSM_X4(r0, r1, r2, r3, addr) \
    asm volatile("ldmatrix.sync.aligned.m8n8.x4.shared.b16 {%0,%1,%2,%3}, [%4];" \
                 : "=r"(r0), "=r"(r1), "=r"(r2), "=r"(r3) : "r"(addr))

__device__ __forceinline__ void mma_f16(float* d, const uint32_t* a, const uint32_t* b) {
    asm volatile(
        "mma.sync.aligned.m16n8k16.row.col.f32.f16.f16.f32 "
        "{%0,%1,%2,%3}, {%4,%5,%6,%7}, {%8,%9}, {%0,%1,%2,%3};\n"
        : "+f"(d[0]), "+f"(d[1]), "+f"(d[2]), "+f"(d[3])
        : "r"(a[0]), "r"(a[1]), "r"(a[2]), "r"(a[3]), "r"(b[0]), "r"(b[1]));
}

// ---------------- GEMM: C[m,n] = sum_k A[m,k]*B[n,k]  (R9-verified) --------
// Block tile 128x256, 256 threads, 8 warps (2x4), warp tile 64x64.
// Register-prefetched globals, double-buffered smem, one barrier per K-tile,
// LDSM fragment loads, m16n8k16 fp16 MMA, fp32 accumulation.
// OutT = __half (GEMM1) or float (GEMM2). M%128==0, N%256==0, K%64==0.
template <typename OutT>
__global__ void __launch_bounds__(256, 1)
gemm_tn(const __half* __restrict__ A, const __half* __restrict__ B,
        OutT* __restrict__ C, int K, int N)
{
    extern __shared__ __align__(16) uint8_t smraw[];
    uint4* sm = reinterpret_cast<uint4*>(smraw);
    const uint32_t sb = smem_u32(smraw);

    const int tid  = threadIdx.x;
    const int lane = tid & 31;
    const int warp = tid >> 5;
    const int wm   = warp & 1;   // 2 warp rows of 64
    const int wn   = warp >> 1;  // 4 warp cols of 64

    const int r = tid >> 3;      // 0..31 : row within group of 32
    const int c = tid & 7;       // 0..7  : 16B (k8) atom within 128B row

    // LDSM per-lane selectors (verified bit-exact since R4):
    const int rsel   = lane & 7;
    const int a_k8hi = lane >> 4;
    const int a_moff = ((lane >> 3) & 1) << 3;
    const int b_k8lo = (lane >> 3) & 1;
    const int b_noff = (lane >> 4) << 3;
    const int mrowA  = wm * 64 + a_moff + rsel;
    const int nrowB  = wn * 64 + b_noff + rsel;

    const size_t mBase = (size_t)blockIdx.y * 128;
    const size_t nBase = (size_t)blockIdx.x * 256;
    const int NK = K / KTILE;

    const __half* Ag = A + (mBase + (size_t)r) * (size_t)K + (size_t)c * 8;
    const __half* Bg = B + (nBase + (size_t)r) * (size_t)K + (size_t)c * 8;

    uint4 pa[4], pb[8];

    auto ldg_tile = [&](int kt) {
        const __half* Ak = Ag + (size_t)kt * KTILE;
        const __half* Bk = Bg + (size_t)kt * KTILE;
        #pragma unroll
        for (int j = 0; j < 4; ++j)
            pa[j] = *(const uint4*)(Ak + (size_t)(j * 32) * K);
        #pragma unroll
        for (int j = 0; j < 8; ++j)
            pb[j] = *(const uint4*)(Bk + (size_t)(j * 32) * K);
    };
    auto sts_tile = [&](int buf) {
        uint4* As = sm + buf * (BUF_BYTES / 16);
        uint4* Bs = As + 1024;
        #pragma unroll
        for (int j = 0; j < 4; ++j) {
            const int m = j * 32 + r;
            As[c * 128 + (m ^ c)] = pa[j];
        }
        #pragma unroll
        for (int j = 0; j < 8; ++j) {
            const int n = j * 32 + r;
            Bs[c * 256 + (n ^ c)] = pb[j];
        }
    };

    float acc[4][8][4];
    #pragma unroll
    for (int i = 0; i < 4; ++i)
        #pragma unroll
        for (int j = 0; j < 8; ++j)
            #pragma unroll
            for (int q = 0; q < 4; ++q) acc[i][j][q] = 0.f;

    // prologue
    ldg_tile(0);
    sts_tile(0);
    if (NK > 1) ldg_tile(1);
    __syncthreads();

    for (int kt = 0; kt < NK; ++kt) {
        if (kt + 1 < NK) {
            sts_tile((kt + 1) & 1);
            if (kt + 2 < NK) ldg_tile(kt + 2);
        }

        const uint32_t abase = sb + (uint32_t)((kt & 1) * BUF_BYTES);
        const uint32_t bbase = abase + 16384;

        #pragma unroll
        for (int ks = 0; ks < 4; ++ks) {        // 4 k16-steps over 64-K tile
            const uint32_t ak8 = (uint32_t)(ks * 2 + a_k8hi);
            const uint32_t bk8 = (uint32_t)(ks * 2 + b_k8lo);

            uint32_t af[4][4];
            #pragma unroll
            for (int im = 0; im < 4; ++im) {
                const uint32_t m = (uint32_t)(mrowA + im * 16);
                const uint32_t addr = abase + (ak8 << 11) + (((m ^ ak8) & 127u) << 4);
                LDSM_X4(af[im][0], af[im][1], af[im][2], af[im][3], addr);
            }
            uint32_t bf[8][2];
            #pragma unroll
            for (int p = 0; p < 4; ++p) {
                const uint32_t n = (uint32_t)(nrowB + p * 16);
                const uint32_t addr = bbase + (bk8 << 12) + (((n ^ bk8) & 255u) << 4);
                LDSM_X4(bf[2 * p][0], bf[2 * p][1], bf[2 * p + 1][0], bf[2 * p + 1][1], addr);
            }
            #pragma unroll
            for (int im = 0; im < 4; ++im)
                #pragma unroll
                for (int jn = 0; jn < 8; ++jn)
                    mma_f16(acc[im][jn], af[im], bf[jn]);
        }
        __syncthreads();
    }

    // Epilogue: fragment layout -> global (pair of cols per quad-lane).
    const int g  = lane >> 2;
    const int q2 = (lane & 3) * 2;
    #pragma unroll
    for (int im = 0; im < 4; ++im) {
        const size_t row0 = mBase + wm * 64 + im * 16 + g;
        #pragma unroll
        for (int jn = 0; jn < 8; ++jn) {
            const size_t col0 = nBase + wn * 64 + jn * 8 + q2;
            if constexpr (sizeof(OutT) == 4) {
                *(float2*)&C[row0 * (size_t)N + col0] =
                    make_float2(acc[im][jn][0], acc[im][jn][1]);
                *(float2*)&C[(row0 + 8) * (size_t)N + col0] =
                    make_float2(acc[im][jn][2], acc[im][jn][3]);
            } else {
                *(__half2*)&C[row0 * (size_t)N + col0] =
                    __floats2half2_rn(acc[im][jn][0], acc[im][jn][1]);
                *(__half2*)&C[(row0 + 8) * (size_t)N + col0] =
                    __floats2half2_rn(acc[im][jn][2], acc[im][jn][3]);
            }
        }
    }
}

// ---------------- fused prepass (one launch) --------------------------------
__device__ __forceinline__ void store_h4(__half* dst, float4 v) {
    __half2* d2 = reinterpret_cast<__half2*>(dst);
    d2[0] = __floats2half2_rn(v.x, v.y);
    d2[1] = __floats2half2_rn(v.z, v.w);
}

#define PREP_S1 ((long)MROWS * HIDDEN / 4)            /* x copy            */
#define PREP_S2 (PREP_S1 + (long)INTER_PAD * HIDDEN / 4) /* gate (pad rows) */
#define PREP_S3 (PREP_S2 + (long)INTER_PAD * HIDDEN / 4) /* up   (pad rows) */
#define PREP_S4 (PREP_S3 + (long)HIDDEN * INTER_PAD / 4) /* w_down pad cols */

__global__ void prep_k(const float* __restrict__ x,
                       const float* __restrict__ wg, const float* __restrict__ wu,
                       const float* __restrict__ wd,
                       __half* __restrict__ dX, __half* __restrict__ dWGU,
                       __half* __restrict__ dWD)
{
    long i = (long)blockIdx.x * blockDim.x + threadIdx.x;
    if (i < PREP_S1) {
        long e = i * 4;
        store_h4(dX + e, *(const float4*)(x + e));
    } else if (i < PREP_S3) {
        // gate rows into dWGU[0..], up rows into dWGU[INTER_PAD*HIDDEN..]
        const bool isUp = (i >= PREP_S2);
        long e = (i - (isUp ? PREP_S2 : PREP_S1)) * 4;
        int row = (int)(e / HIDDEN);
        float4 v = make_float4(0.f, 0.f, 0.f, 0.f);
        if (row < INTER) {
            const float* src = isUp ? wu : wg;
            v = *(const float4*)(src + (size_t)row * HIDDEN + (e % HIDDEN));
        }
        store_h4(dWGU + (isUp ? (size_t)INTER_PAD * HIDDEN : 0) + e, v);
    } else if (i < PREP_S4) {
        long e = (i - PREP_S3) * 4;
        int row = (int)(e / INTER_PAD);
        int col = (int)(e % INTER_PAD);
        float4 v = make_float4(0.f, 0.f, 0.f, 0.f);
        if (col < INTER)
            v = *(const float4*)(wd + (size_t)row * INTER + col);
        store_h4(dWD + e, v);
    }
}

// ---------------- combine: vectorized (8 cols per thread) -------------------
// Reads fp16 GU (gate col i, up col INTER_PAD+i), fp32 math, writes fp16 C.
#define CCOL8 (INTER_PAD / 8)   /* 704 uint4 chunks per row */

__device__ __forceinline__ void h8_to_f(const uint4 q, float* f) {
    const __half2* h2 = reinterpret_cast<const __half2*>(&q);
    #pragma unroll
    for (int j = 0; j < 4; ++j) {
        float2 v = __half22float2(h2[j]);
        f[2 * j] = v.x; f[2 * j + 1] = v.y;
    }
}

__global__ void combine_k()
{
    const long total8 = (long)BSROWS * CCOL8;
    long idx = (long)blockIdx.x * blockDim.x + threadIdx.x;
    if (idx >= total8) return;

    const int row  = (int)(idx / CCOL8);
    const int col  = (int)(idx % CCOL8) * 8;
    const size_t rstride = (size_t)BSROWS * NFUSED;     // t-slab stride in GU
    const size_t cstride = (size_t)BSROWS * INTER_PAD;  // t-slab stride in C

    float gv[TSTEPS][8], uv[TSTEPS][8];
    #pragma unroll
    for (int t = 0; t < TSTEPS; ++t) {
        const __half* base = g_GU + (size_t)t * rstride + (size_t)row * NFUSED;
        h8_to_f(*(const uint4*)(base + col),             gv[t]);
        h8_to_f(*(const uint4*)(base + INTER_PAD + col), uv[t]);
    }

    float outv[TSTEPS][8];
    #pragma unroll
    for (int j = 0; j < 8; ++j) {
        float X = 0.f, Yprev = 0.f, SB = 0.f;
        float Av[TSTEPS];
        #pragma unroll
        for (int t = 0; t < TSTEPS; ++t) {
            X += gv[t][j];
            const float Y = X / (1.f + expf(-X));   // silu of cumsum
            Av[t] = Y - Yprev;
            Yprev = Y;
            SB += uv[t][j];
        }
        const float SA = Yprev;                     // telescoping sum of A
        #pragma unroll
        for (int t = 0; t < TSTEPS; ++t)
            outv[t][j] = 0.5f * (Av[t] * SB + uv[t][j] * SA);
    }

    #pragma unroll
    for (int t = 0; t < TSTEPS; ++t) {
        uint4 q;
        __half2* h2 = reinterpret_cast<__half2*>(&q);
        #pragma unroll
        for (int j = 0; j < 4; ++j)
            h2[j] = __floats2half2_rn(outv[t][2 * j], outv[t][2 * j + 1]);
        *(uint4*)(g_C + (size_t)t * cstride + (size_t)row * INTER_PAD + col) = q;
    }
}

// ---------------- launch -----------------------------------------------------
extern "C" void kernel_launch(void* const* d_in, const int* in_sizes, int n_in,
                              void* d_out, int out_size)
{
    const float* x      = (const float*)d_in[0];
    const float* w_gate = (const float*)d_in[1];
    const float* w_up   = (const float*)d_in[2];
    const float* w_down = (const float*)d_in[3];
    float* out = (float*)d_out;
    (void)in_sizes; (void)n_in; (void)out_size;

    __half *dX, *dWGU, *dWD, *dGU, *dC;
    cudaGetSymbolAddress((void**)&dX,   g_X);
    cudaGetSymbolAddress((void**)&dWGU, g_WGU);
    cudaGetSymbolAddress((void**)&dWD,  g_WD);
    cudaGetSymbolAddress((void**)&dGU,  g_GU);
    cudaGetSymbolAddress((void**)&dC,   g_C);

    cudaFuncSetAttribute(gemm_tn<__half>, cudaFuncAttributeMaxDynamicSharedMemorySize, DYN_SMEM);
    cudaFuncSetAttribute(gemm_tn<float>,  cudaFuncAttributeMaxDynamicSharedMemorySize, DYN_SMEM);

    // Fused prepass (one launch): fp32 -> fp16, weight pad/concat.
    prep_k<<<(unsigned)((PREP_S4 + 255) / 256), 256>>>(x, w_gate, w_up, w_down,
                                                       dX, dWGU, dWD);

    // Fused gate+up projection: (4096 x 11264) = x(4096x2048) @ [WG;WU]^T -> fp16
    {
        dim3 grid(NFUSED / 256, MROWS / 128);      // 44 x 32
        gemm_tn<__half><<<grid, 256, DYN_SMEM>>>(dX, dWGU, dGU, HIDDEN, NFUSED);
    }

    // Combine (vectorized: 8 cols/thread, fp32 math, fp16 out).
    {
        long total8 = (long)BSROWS * CCOL8;
        combine_k<<<(unsigned)((total8 + 255) / 256), 256>>>();
    }

    // Down projection: (4096 x 2048) = C(4096x5632) @ w_down'^T -> fp32 out
    {
        dim3 grid(HIDDEN / 256, MROWS / 128);      // 8 x 32
        gemm_tn<float><<<grid, 256, DYN_SMEM>>>(dC, dWD, out, INTER_PAD, HIDDEN);
    }
}